// round 3
// baseline (speedup 1.0000x reference)
#include <cuda_runtime.h>

#define NMAX 100000
#define EMAX 1200000
#define DIM 64

// -------- persistent scratch (device globals: allocation-free) --------
__device__ int   g_deg[NMAX];
__device__ int   g_excl[NMAX];
__device__ int   g_bsum[128];
__device__ int   g_rowstart[NMAX + 1];
__device__ int   g_cursor[NMAX];
__device__ float g_dinv[NMAX];
__device__ float g_sd[NMAX];
__device__ int   g_csr[EMAX];
__device__ float g_A[(size_t)NMAX * DIM];
__device__ float g_B[(size_t)NMAX * DIM];
__device__ int   g_is64;

// -------- helpers --------
__device__ __forceinline__ float eluf(float v) {
    return v > 0.0f ? v : expm1f(v);
}

__device__ __forceinline__ unsigned long long splat2(float s) {
    unsigned long long r;
    asm("mov.b64 %0, {%1, %1};" : "=l"(r) : "f"(s));
    return r;
}
__device__ __forceinline__ unsigned long long pack2(float x, float y) {
    unsigned long long r;
    asm("mov.b64 %0, {%1, %2};" : "=l"(r) : "f"(x), "f"(y));
    return r;
}
__device__ __forceinline__ float2 unpack2(unsigned long long v) {
    float2 r;
    asm("mov.b64 {%0, %1}, %2;" : "=f"(r.x), "=f"(r.y) : "l"(v));
    return r;
}
__device__ __forceinline__ unsigned long long ffma2(unsigned long long a,
                                                    unsigned long long b,
                                                    unsigned long long c) {
    unsigned long long d;
    asm("fma.rn.f32x2 %0, %1, %2, %3;" : "=l"(d) : "l"(a), "l"(b), "l"(c));
    return d;
}

// -------- K0: detect int64 vs int32 edge_index (robust, 16 samples) --------
__global__ void k_detect(const void* edges, int n_edges, int n_nodes) {
    if (threadIdx.x == 0 && blockIdx.x == 0) {
        const long long* p64 = (const long long*)edges;
        int ok64 = 1;
        int step = n_edges / 16; if (step < 1) step = 1;
        for (int i = 0; i < 16; i++) {
            long long idx = (long long)i * step;
            if (idx >= n_edges) break;
            long long v = p64[idx];
            if (v < 0 || v >= (long long)n_nodes) { ok64 = 0; break; }
        }
        g_is64 = ok64;
    }
}

__device__ __forceinline__ int edge_src(const void* edges, int n_edges, int e, int is64) {
    if (is64) return (int)((const long long*)edges)[e];
    return ((const int*)edges)[e];
}
__device__ __forceinline__ int edge_dst(const void* edges, int n_edges, int e, int is64) {
    if (is64) return (int)((const long long*)edges)[(size_t)n_edges + e];
    return ((const int*)edges)[(size_t)n_edges + e];
}
__device__ __forceinline__ int clampi(int v, int n) {
    return v < 0 ? 0 : (v >= n ? n - 1 : v);
}

// -------- K1: zero degree counters --------
__global__ void k_zero(int n) {
    int i = blockIdx.x * blockDim.x + threadIdx.x;
    if (i < n) g_deg[i] = 0;
}

// -------- K2: count in-degree --------
__global__ void k_count(const void* edges, int n_edges, int n_nodes) {
    int e = blockIdx.x * blockDim.x + threadIdx.x;
    if (e >= n_edges) return;
    int is64 = g_is64;
    int v = clampi(edge_dst(edges, n_edges, e, is64), n_nodes);
    atomicAdd(&g_deg[v], 1);
}

// -------- K3a/b/c: exclusive scan of degrees --------
__global__ void k_scan1(int n) {
    __shared__ int smi[1024];
    int t = threadIdx.x;
    int i = blockIdx.x * 1024 + t;
    int v = (i < n) ? g_deg[i] : 0;
    smi[t] = v;
    __syncthreads();
    for (int off = 1; off < 1024; off <<= 1) {
        int a = (t >= off) ? smi[t - off] : 0;
        __syncthreads();
        smi[t] += a;
        __syncthreads();
    }
    if (i < n) g_excl[i] = smi[t] - v;
    if (t == 1023 && blockIdx.x < 128) g_bsum[blockIdx.x] = smi[1023];
}

__global__ void k_scan2(int nb) {
    __shared__ int smi[128];
    int t = threadIdx.x;
    int v = (t < nb && t < 128) ? g_bsum[t] : 0;
    smi[t] = v;
    __syncthreads();
    for (int off = 1; off < 128; off <<= 1) {
        int a = (t >= off) ? smi[t - off] : 0;
        __syncthreads();
        smi[t] += a;
        __syncthreads();
    }
    if (t < nb && t < 128) g_bsum[t] = smi[t] - v;  // exclusive
}

__global__ void k_scan3(int n, int n_edges) {
    int i = blockIdx.x * blockDim.x + threadIdx.x;
    if (i < n) {
        int rs = g_excl[i] + g_bsum[i >> 10];
        g_rowstart[i] = rs;
        g_cursor[i]   = rs;
        g_dinv[i]     = rsqrtf((float)(g_deg[i] + 1));
    }
    if (i == 0) g_rowstart[n] = n_edges;
}

// -------- K4: scatter edges into CSR-by-dst --------
__global__ void k_fill(const void* edges, int n_edges, int n_nodes) {
    int e = blockIdx.x * blockDim.x + threadIdx.x;
    if (e >= n_edges) return;
    int is64 = g_is64;
    int u = clampi(edge_src(edges, n_edges, e, is64), n_nodes);
    int v = clampi(edge_dst(edges, n_edges, e, is64), n_nodes);
    int p = atomicAdd(&g_cursor[v], 1);
    if (p >= 0 && p < n_edges) g_csr[p] = u;
}

// -------- K5: gather aggregation (warp per node) --------
__global__ void __launch_bounds__(256) k_gather(const float* __restrict__ x, int n) {
    int warp = (blockIdx.x * blockDim.x + threadIdx.x) >> 5;
    int lane = threadIdx.x & 31;
    if (warp >= n) return;
    int v = warp;
    int s = g_rowstart[v];
    int e = g_rowstart[v + 1];
    float2 aA = make_float2(0.f, 0.f);
    float2 aB = make_float2(0.f, 0.f);
    float sd = 0.f;
    for (int base = s; base < e; base += 32) {
        int idx = base + lane;
        int u = 0; float du = 0.f;
        if (idx < e) { u = g_csr[idx]; du = g_dinv[u]; }
        int cnt = min(32, e - base);
        for (int i = 0; i < cnt; i++) {
            int   uu = __shfl_sync(0xffffffffu, u, i);
            float dd = __shfl_sync(0xffffffffu, du, i);
            float2 xu = *(const float2*)(x + (size_t)uu * DIM + 2 * lane);
            aA.x += xu.x; aA.y += xu.y;
            aB.x = fmaf(dd, xu.x, aB.x);
            aB.y = fmaf(dd, xu.y, aB.y);
            sd += dd;
        }
    }
    *(float2*)(g_A + (size_t)v * DIM + 2 * lane) = aA;
    *(float2*)(g_B + (size_t)v * DIM + 2 * lane) = aB;
    if (lane == 0) g_sd[v] = sd;
}

// -------- K6: fused 4x(64x64) matvec + elu + mix --------
// block = 128 threads (4 warps); each warp handles 8 nodes per tile pass.
// smem: 4 weight mats (64KB) + biases + per-warp input staging (float4 per k).
__global__ void __launch_bounds__(128) k_gemm(
    const float* __restrict__ x, float* __restrict__ out,
    const float* __restrict__ Wg, const float* __restrict__ bg,
    const float* __restrict__ Ws, const float* __restrict__ Wn,
    const float* __restrict__ bs,
    const float* __restrict__ Wi, const float* __restrict__ bi,
    const float* __restrict__ wmix, int n)
{
    extern __shared__ float sm[];
    float*  sW    = sm;                    // 16384 floats
    float*  sBias = sm + 16384;            // 192 floats
    float*  sC    = sBias + 192;           // 32 floats
    float4* sIn   = (float4*)(sC + 32);    // 4 warps * 8 nodes * 64 float4

    int t = threadIdx.x;
    {
        float4* d4 = (float4*)sW;
        const float4* s4;
        s4 = (const float4*)Wg; for (int i = t; i < 1024; i += 128) d4[i]        = s4[i];
        s4 = (const float4*)Ws; for (int i = t; i < 1024; i += 128) d4[1024 + i] = s4[i];
        s4 = (const float4*)Wn; for (int i = t; i < 1024; i += 128) d4[2048 + i] = s4[i];
        s4 = (const float4*)Wi; for (int i = t; i < 1024; i += 128) d4[3072 + i] = s4[i];
        for (int i = t; i < 64; i += 128) {
            sBias[i]       = bg[i];
            sBias[64 + i]  = bs[i];
            sBias[128 + i] = bi[i];
        }
    }
    __syncthreads();

    float wm0 = wmix[0], wm1 = wmix[1], wm2 = wmix[2];
    int warp = t >> 5, lane = t & 31;
    int tile_stride = gridDim.x * 32;

    for (int tbase = blockIdx.x * 32; tbase < n; tbase += tile_stride) {
        int vbase = tbase + warp * 8;

        // stage inputs: per node k-indexed float4 {P_k, x_k, Q_k, R_k}
        #pragma unroll
        for (int nn = 0; nn < 8; nn++) {
            int v = vbase + nn;
            float4 st0 = make_float4(0.f, 0.f, 0.f, 0.f);
            float4 st1 = make_float4(0.f, 0.f, 0.f, 0.f);
            float c = 0.f;
            if (v < n) {
                float2 xv = *(const float2*)(x   + (size_t)v * DIM + 2 * lane);
                float2 a  = *(const float2*)(g_A + (size_t)v * DIM + 2 * lane);
                float2 b  = *(const float2*)(g_B + (size_t)v * DIM + 2 * lane);
                float di  = g_dinv[v];
                float sd  = g_sd[v];
                float degf = (float)(g_rowstart[v + 1] - g_rowstart[v]);
                float im  = 1.0f / fmaxf(degf, 1.0f);
                float di2 = di * di;
                st0 = make_float4(di * b.x + di2 * xv.x, xv.x, a.x * im, xv.x + a.x);
                st1 = make_float4(di * b.y + di2 * xv.y, xv.y, a.y * im, xv.y + a.y);
                c = di * sd + di2;
            }
            sIn[(warp * 8 + nn) * 64 + 2 * lane]     = st0;
            sIn[(warp * 8 + nn) * 64 + 2 * lane + 1] = st1;
            if (lane == 0) sC[warp * 8 + nn] = c;
        }
        __syncwarp();

        unsigned long long aG[8], aS[8], aI[8];
        unsigned long long bg2 = pack2(sBias[2 * lane],       sBias[2 * lane + 1]);
        unsigned long long bs2 = pack2(sBias[64 + 2 * lane],  sBias[64 + 2 * lane + 1]);
        unsigned long long bi2 = pack2(sBias[128 + 2 * lane], sBias[128 + 2 * lane + 1]);
        #pragma unroll
        for (int nn = 0; nn < 8; nn++) {
            float c = sC[warp * 8 + nn];
            aG[nn] = ffma2(splat2(c), bg2, splat2(0.0f));
            aS[nn] = bs2;
            aI[nn] = bi2;
        }

        #pragma unroll 2
        for (int k = 0; k < 64; k++) {
            unsigned long long wg = *(const unsigned long long*)&sW[k * 64 + 2 * lane];
            unsigned long long ws = *(const unsigned long long*)&sW[4096  + k * 64 + 2 * lane];
            unsigned long long wn = *(const unsigned long long*)&sW[8192  + k * 64 + 2 * lane];
            unsigned long long wi = *(const unsigned long long*)&sW[12288 + k * 64 + 2 * lane];
            #pragma unroll
            for (int nn = 0; nn < 8; nn++) {
                float4 in4 = sIn[(warp * 8 + nn) * 64 + k];
                aG[nn] = ffma2(splat2(in4.x), wg, aG[nn]);
                aS[nn] = ffma2(splat2(in4.y), ws, aS[nn]);
                aS[nn] = ffma2(splat2(in4.z), wn, aS[nn]);
                aI[nn] = ffma2(splat2(in4.w), wi, aI[nn]);
            }
        }

        #pragma unroll
        for (int nn = 0; nn < 8; nn++) {
            int v = vbase + nn;
            if (v < n) {
                float2 g  = unpack2(aG[nn]);
                float2 s2 = unpack2(aS[nn]);
                float2 gi = unpack2(aI[nn]);
                float2 o;
                o.x = wm0 * eluf(g.x) + wm1 * eluf(s2.x) + wm2 * eluf(gi.x);
                o.y = wm0 * eluf(g.y) + wm1 * eluf(s2.y) + wm2 * eluf(gi.y);
                *(float2*)(out + (size_t)v * DIM + 2 * lane) = o;
            }
        }
        __syncwarp();
    }
}

// -------- launch --------
extern "C" void kernel_launch(void* const* d_in, const int* in_sizes, int n_in,
                              void* d_out, int out_size) {
    const float* x    = (const float*)d_in[0];
    // d_in[1] = x0 (unused by reference)
    const float* wmix = (const float*)d_in[2];
    const void*  edges = d_in[3];
    const float* Wg = (const float*)d_in[4];
    const float* bg = (const float*)d_in[5];
    const float* Ws = (const float*)d_in[6];
    const float* Wn = (const float*)d_in[7];
    const float* bs = (const float*)d_in[8];
    const float* Wi = (const float*)d_in[9];
    const float* bi = (const float*)d_in[10];
    float* out = (float*)d_out;

    int n  = in_sizes[0] / DIM;
    int ne = in_sizes[3] / 2;
    if (n > NMAX) n = NMAX;
    if (ne > EMAX) ne = EMAX;

    size_t smem = (size_t)(16384 + 192 + 32) * sizeof(float) + (size_t)2048 * sizeof(float4);
    cudaFuncSetAttribute(k_gemm, cudaFuncAttributeMaxDynamicSharedMemorySize, (int)smem);

    k_detect<<<1, 32>>>(edges, ne, n);
    k_zero<<<(n + 255) / 256, 256>>>(n);
    k_count<<<(ne + 255) / 256, 256>>>(edges, ne, n);
    int nb1024 = (n + 1023) / 1024;
    k_scan1<<<nb1024, 1024>>>(n);
    k_scan2<<<1, 128>>>(nb1024);
    k_scan3<<<nb1024, 1024>>>(n, ne);
    k_fill<<<(ne + 255) / 256, 256>>>(edges, ne, n);
    k_gather<<<(n + 7) / 8, 256>>>(x, n);
    k_gemm<<<296, 128, smem>>>(x, out, Wg, bg, Ws, Wn, bs, Wi, bi, wmix, n);
}

// round 5
// speedup vs baseline: 1.0381x; 1.0381x over previous
#include <cuda_runtime.h>

#define NMAX 100000
#define EMAX 1200000
#define DIM 64

// -------- persistent scratch (device globals: allocation-free) --------
__device__ int   g_deg[NMAX];
__device__ int   g_excl[NMAX];
__device__ int   g_bsum[128];
__device__ int   g_rowstart[NMAX + 1];
__device__ int   g_cursor[NMAX];
__device__ float g_dinv[NMAX];
__device__ float g_sd[NMAX];
__device__ int   g_csr[EMAX];
__device__ float g_A[(size_t)NMAX * DIM];
__device__ float g_B[(size_t)NMAX * DIM];
__device__ float g_zero[DIM];
__device__ int   g_is64;

// -------- helpers --------
__device__ __forceinline__ float eluf(float v) {
    return v > 0.0f ? v : expm1f(v);
}
__device__ __forceinline__ unsigned long long pack2(float x, float y) {
    unsigned long long r;
    asm("mov.b64 %0, {%1, %2};" : "=l"(r) : "f"(x), "f"(y));
    return r;
}
__device__ __forceinline__ float2 unpack2(unsigned long long v) {
    float2 r;
    asm("mov.b64 {%0, %1}, %2;" : "=f"(r.x), "=f"(r.y) : "l"(v));
    return r;
}
__device__ __forceinline__ unsigned long long ffma2(unsigned long long a,
                                                    unsigned long long b,
                                                    unsigned long long c) {
    unsigned long long d;
    asm("fma.rn.f32x2 %0, %1, %2, %3;" : "=l"(d) : "l"(a), "l"(b), "l"(c));
    return d;
}

// -------- K0: detect int64 vs int32 edge_index (robust, 16 samples) --------
__global__ void k_detect(const void* edges, int n_edges, int n_nodes) {
    if (threadIdx.x == 0 && blockIdx.x == 0) {
        const long long* p64 = (const long long*)edges;
        int ok64 = 1;
        int step = n_edges / 16; if (step < 1) step = 1;
        for (int i = 0; i < 16; i++) {
            long long idx = (long long)i * step;
            if (idx >= n_edges) break;
            long long v = p64[idx];
            if (v < 0 || v >= (long long)n_nodes) { ok64 = 0; break; }
        }
        g_is64 = ok64;
    }
}

__device__ __forceinline__ int edge_src(const void* edges, int n_edges, int e, int is64) {
    if (is64) return (int)((const long long*)edges)[e];
    return ((const int*)edges)[e];
}
__device__ __forceinline__ int edge_dst(const void* edges, int n_edges, int e, int is64) {
    if (is64) return (int)((const long long*)edges)[(size_t)n_edges + e];
    return ((const int*)edges)[(size_t)n_edges + e];
}
__device__ __forceinline__ int clampi(int v, int n) {
    return v < 0 ? 0 : (v >= n ? n - 1 : v);
}

// -------- K1: zero degree counters + zero row --------
__global__ void k_zero(int n) {
    int i = blockIdx.x * blockDim.x + threadIdx.x;
    if (i < n) g_deg[i] = 0;
    if (i < DIM) g_zero[i] = 0.0f;
}

// -------- K2: count in-degree --------
__global__ void k_count(const void* edges, int n_edges, int n_nodes) {
    int e = blockIdx.x * blockDim.x + threadIdx.x;
    if (e >= n_edges) return;
    int is64 = g_is64;
    int v = clampi(edge_dst(edges, n_edges, e, is64), n_nodes);
    atomicAdd(&g_deg[v], 1);
}

// -------- K3a/b/c: exclusive scan of degrees (warp-shuffle based) --------
__global__ void k_scan1(int n) {
    __shared__ int warp_sums[32];
    int t = threadIdx.x;
    int lane = t & 31, warp = t >> 5;
    int i = blockIdx.x * 1024 + t;
    int v = (i < n) ? g_deg[i] : 0;
    // inclusive warp scan
    int sc = v;
    #pragma unroll
    for (int off = 1; off < 32; off <<= 1) {
        int a = __shfl_up_sync(0xffffffffu, sc, off);
        if (lane >= off) sc += a;
    }
    if (lane == 31) warp_sums[warp] = sc;
    __syncthreads();
    if (warp == 0) {
        int ws = warp_sums[lane];
        int wsc = ws;
        #pragma unroll
        for (int off = 1; off < 32; off <<= 1) {
            int a = __shfl_up_sync(0xffffffffu, wsc, off);
            if (lane >= off) wsc += a;
        }
        warp_sums[lane] = wsc - ws;  // exclusive
    }
    __syncthreads();
    int incl = sc + warp_sums[warp];
    if (i < n) g_excl[i] = incl - v;
    if (t == 1023 && blockIdx.x < 128) g_bsum[blockIdx.x] = incl;
}

__global__ void k_scan2(int nb) {
    __shared__ int smi[128];
    int t = threadIdx.x;
    int v = (t < nb && t < 128) ? g_bsum[t] : 0;
    smi[t] = v;
    __syncthreads();
    for (int off = 1; off < 128; off <<= 1) {
        int a = (t >= off) ? smi[t - off] : 0;
        __syncthreads();
        smi[t] += a;
        __syncthreads();
    }
    if (t < nb && t < 128) g_bsum[t] = smi[t] - v;  // exclusive
}

__global__ void k_scan3(int n, int n_edges) {
    int i = blockIdx.x * blockDim.x + threadIdx.x;
    if (i < n) {
        int rs = g_excl[i] + g_bsum[i >> 10];
        g_rowstart[i] = rs;
        g_cursor[i]   = rs;
        g_dinv[i]     = rsqrtf((float)(g_deg[i] + 1));
    }
    if (i == 0) g_rowstart[n] = n_edges;
}

// -------- K4: scatter edges into CSR-by-dst --------
__global__ void k_fill(const void* edges, int n_edges, int n_nodes) {
    int e = blockIdx.x * blockDim.x + threadIdx.x;
    if (e >= n_edges) return;
    int is64 = g_is64;
    int u = clampi(edge_src(edges, n_edges, e, is64), n_nodes);
    int v = clampi(edge_dst(edges, n_edges, e, is64), n_nodes);
    int p = atomicAdd(&g_cursor[v], 1);
    if (p >= 0 && p < n_edges) g_csr[p] = u;
}

// -------- K5: gather aggregation (warp per node, 8-wide unrolled MLP) --------
__global__ void __launch_bounds__(256) k_gather(const float* __restrict__ x, int n) {
    int warp = (blockIdx.x * blockDim.x + threadIdx.x) >> 5;
    int lane = threadIdx.x & 31;
    if (warp >= n) return;
    int v = warp;
    int s = g_rowstart[v];
    int e = g_rowstart[v + 1];
    const float* zrow = g_zero;
    float2 aA = make_float2(0.f, 0.f);
    float2 aB = make_float2(0.f, 0.f);
    float sd = 0.f;
    for (int base = s; base < e; base += 32) {
        int idx = base + lane;
        int u = 0; float du = 0.f;
        if (idx < e) { u = g_csr[idx]; du = g_dinv[u]; }
        int m  = min(32, e - base);
        int m8 = (m + 7) & ~7;
        for (int i = 0; i < m8; i += 8) {
            #pragma unroll
            for (int j = 0; j < 8; j++) {
                int   uu = __shfl_sync(0xffffffffu, u,  i + j);
                float dd = __shfl_sync(0xffffffffu, du, i + j);
                bool  vj = (base + i + j) < e;
                const float* rp = vj ? (x + (size_t)uu * DIM) : zrow;
                float2 xu = *(const float2*)(rp + 2 * lane);
                aA.x += xu.x; aA.y += xu.y;
                aB.x = fmaf(dd, xu.x, aB.x);
                aB.y = fmaf(dd, xu.y, aB.y);
                sd += dd;
            }
        }
    }
    *(float2*)(g_A + (size_t)v * DIM + 2 * lane) = aA;
    *(float2*)(g_B + (size_t)v * DIM + 2 * lane) = aB;
    if (lane == 0) g_sd[v] = sd;
}

// -------- K6: fused 4x(64x64) matvec + elu + mix (paired-stream FFMA2) --------
// Streams packed per f32x2 lane: pairA = {GCN: P.Wg, SAGEself: x.Ws},
//                                pairB = {SAGEneigh: Q.Wn, GIN: R.Wi}.
// Weights pre-interleaved in smem so no splat MOVs are needed.
// block = 128 threads (4 warps); each warp handles 8 nodes per tile pass.
__global__ void __launch_bounds__(128) k_gemm(
    const float* __restrict__ x, float* __restrict__ out,
    const float* __restrict__ Wg, const float* __restrict__ bg,
    const float* __restrict__ Ws, const float* __restrict__ Wn,
    const float* __restrict__ bs,
    const float* __restrict__ Wi, const float* __restrict__ bi,
    const float* __restrict__ wmix, int n)
{
    extern __shared__ float sm[];
    float2* sWA   = (float2*)sm;                   // 4096 f32x2 {Wg,Ws}
    float2* sWB   = sWA + 4096;                    // 4096 f32x2 {Wn,Wi}
    float*  sBias = (float*)(sWB + 4096);          // 192 floats
    float*  sC    = sBias + 192;                   // 32 floats
    float4* sIn   = (float4*)(sC + 32);            // 32 slots * 64 float4

    int t = threadIdx.x;
    for (int i = t; i < 4096; i += 128) {
        sWA[i] = make_float2(Wg[i], Ws[i]);
        sWB[i] = make_float2(Wn[i], Wi[i]);
    }
    for (int i = t; i < 64; i += 128) {
        sBias[i]       = bg[i];
        sBias[64 + i]  = bs[i];
        sBias[128 + i] = bi[i];
    }
    __syncthreads();

    float wm0 = wmix[0], wm1 = wmix[1], wm2 = wmix[2];
    int warp = t >> 5, lane = t & 31;
    int c0 = 2 * lane, c1 = 2 * lane + 1;
    int tile_stride = gridDim.x * 32;

    for (int tbase = blockIdx.x * 32; tbase < n; tbase += tile_stride) {
        int vbase = tbase + warp * 8;

        // stage inputs: per node k-indexed float4 {P_k, x_k, Q_k, R_k}
        #pragma unroll
        for (int nn = 0; nn < 8; nn++) {
            int v = vbase + nn;
            float4 st0 = make_float4(0.f, 0.f, 0.f, 0.f);
            float4 st1 = make_float4(0.f, 0.f, 0.f, 0.f);
            float c = 0.f;
            if (v < n) {
                float2 xv = *(const float2*)(x   + (size_t)v * DIM + c0);
                float2 a  = *(const float2*)(g_A + (size_t)v * DIM + c0);
                float2 b  = *(const float2*)(g_B + (size_t)v * DIM + c0);
                float di  = g_dinv[v];
                float sdv = g_sd[v];
                float degf = (float)(g_rowstart[v + 1] - g_rowstart[v]);
                float im  = 1.0f / fmaxf(degf, 1.0f);
                float di2 = di * di;
                st0 = make_float4(di * b.x + di2 * xv.x, xv.x, a.x * im, xv.x + a.x);
                st1 = make_float4(di * b.y + di2 * xv.y, xv.y, a.y * im, xv.y + a.y);
                c = di * sdv + di2;
            }
            sIn[(warp * 8 + nn) * 64 + c0]     = st0;
            sIn[(warp * 8 + nn) * 64 + c0 + 1] = st1;
            if (lane == 0) sC[warp * 8 + nn] = c;
        }
        __syncwarp();

        // accumulators: accA = {G, S_self}, accB = {S_neigh, I} for cols c0,c1
        unsigned long long accA[8][2], accB[8][2];
        float bg0 = sBias[c0], bg1 = sBias[c1];
        float bs0 = sBias[64 + c0], bs1 = sBias[64 + c1];
        float bi0 = sBias[128 + c0], bi1 = sBias[128 + c1];
        #pragma unroll
        for (int nn = 0; nn < 8; nn++) {
            float c = sC[warp * 8 + nn];
            accA[nn][0] = pack2(c * bg0, bs0);
            accA[nn][1] = pack2(c * bg1, bs1);
            accB[nn][0] = pack2(0.0f, bi0);
            accB[nn][1] = pack2(0.0f, bi1);
        }

        const ulonglong2* sIn2 = (const ulonglong2*)sIn;
        const ulonglong2* wA2  = (const ulonglong2*)sWA;
        const ulonglong2* wB2  = (const ulonglong2*)sWB;
        int slot = warp * 8;

        #pragma unroll 2
        for (int k = 0; k < 64; k++) {
            ulonglong2 wA = wA2[(k * 64 + c0) >> 1];  // {wA[c0], wA[c1]}
            ulonglong2 wB = wB2[(k * 64 + c0) >> 1];
            #pragma unroll
            for (int nn = 0; nn < 8; nn++) {
                ulonglong2 in2 = sIn2[(slot + nn) * 64 + k];  // {{P,x},{Q,R}}
                accA[nn][0] = ffma2(in2.x, wA.x, accA[nn][0]);
                accA[nn][1] = ffma2(in2.x, wA.y, accA[nn][1]);
                accB[nn][0] = ffma2(in2.y, wB.x, accB[nn][0]);
                accB[nn][1] = ffma2(in2.y, wB.y, accB[nn][1]);
            }
        }

        #pragma unroll
        for (int nn = 0; nn < 8; nn++) {
            int v = vbase + nn;
            if (v < n) {
                float2 a0 = unpack2(accA[nn][0]);
                float2 a1 = unpack2(accA[nn][1]);
                float2 b0 = unpack2(accB[nn][0]);
                float2 b1 = unpack2(accB[nn][1]);
                float2 o;
                o.x = wm0 * eluf(a0.x) + wm1 * eluf(a0.y + b0.x) + wm2 * eluf(b0.y);
                o.y = wm0 * eluf(a1.x) + wm1 * eluf(a1.y + b1.x) + wm2 * eluf(b1.y);
                *(float2*)(out + (size_t)v * DIM + c0) = o;
            }
        }
        __syncwarp();
    }
}

// -------- launch --------
extern "C" void kernel_launch(void* const* d_in, const int* in_sizes, int n_in,
                              void* d_out, int out_size) {
    const float* x    = (const float*)d_in[0];
    // d_in[1] = x0 (unused by reference)
    const float* wmix = (const float*)d_in[2];
    const void*  edges = d_in[3];
    const float* Wg = (const float*)d_in[4];
    const float* bg = (const float*)d_in[5];
    const float* Ws = (const float*)d_in[6];
    const float* Wn = (const float*)d_in[7];
    const float* bs = (const float*)d_in[8];
    const float* Wi = (const float*)d_in[9];
    const float* bi = (const float*)d_in[10];
    float* out = (float*)d_out;

    int n  = in_sizes[0] / DIM;
    int ne = in_sizes[3] / 2;
    if (n > NMAX) n = NMAX;
    if (ne > EMAX) ne = EMAX;

    // smem: 8192 f32x2 (64KB) + 224 floats + 2048 float4 (32KB)
    size_t smem = (size_t)8192 * sizeof(float2) + (size_t)224 * sizeof(float)
                + (size_t)2048 * sizeof(float4);
    cudaFuncSetAttribute(k_gemm, cudaFuncAttributeMaxDynamicSharedMemorySize, (int)smem);

    k_detect<<<1, 32>>>(edges, ne, n);
    k_zero<<<(n + 255) / 256, 256>>>(n);
    k_count<<<(ne + 255) / 256, 256>>>(edges, ne, n);
    int nb1024 = (n + 1023) / 1024;
    k_scan1<<<nb1024, 1024>>>(n);
    k_scan2<<<1, 128>>>(nb1024);
    k_scan3<<<nb1024, 1024>>>(n, ne);
    k_fill<<<(ne + 255) / 256, 256>>>(edges, ne, n);
    k_gather<<<(n + 7) / 8, 256>>>(x, n);
    k_gemm<<<296, 128, smem>>>(x, out, Wg, bg, Ws, Wn, bs, Wi, bi, wmix, n);
}